// round 4
// baseline (speedup 1.0000x reference)
#include <cuda_runtime.h>
#include <math.h>

constexpr int NN   = 50000;
constexpr int EE   = 500000;
constexpr int TT   = 3;
constexpr int RR   = 4;
constexpr int HH   = 8;
constexpr int NH_  = 128;
constexpr int LL   = 2;
constexpr int DIN_ = 166;
constexpr int MT_  = 240;

static int cdiv(int a, int b) { return (a + b - 1) / b; }

// ---------------- device scratch (no cudaMalloc allowed) ----------------
__device__ float g_h   [NN*NH_];
__device__ float g_h2  [NN*NH_];
__device__ float g_q   [NN*NH_];
__device__ float g_kn  [NN*NH_];
__device__ float g_vn  [NN*NH_];
__device__ float g_qrel[NN*RR*NH_];   // [n][r][h*16+d]
__device__ float g_agg [NN*NH_];      // normalized aggregate
__device__ float g_sin [MT_*NH_];
__device__ float g_t240[MT_*NH_];
__device__ float g_kt  [MT_*TT*NH_];
__device__ float g_vt  [MT_*TT*NH_];
__device__ int   g_cnt[TT], g_off[TT], g_fill[TT];
__device__ int   g_order[NN];
// CSR by target
__device__ int   g_deg [NN];
__device__ int   g_rowptr[NN+1];
__device__ int   g_dfill[NN];
__device__ int   g_esrc[EE];
__device__ int   g_epk [EE];          // (ko << 2) | r

// ---------------- prologue kernels ----------------
__global__ void k_init() {
    int i = threadIdx.x;
    if (i < TT) { g_cnt[i] = 0; g_fill[i] = 0; }
}
__global__ void k_count(const int* __restrict__ nt) {
    int i = blockIdx.x * blockDim.x + threadIdx.x;
    if (i < NN) atomicAdd(&g_cnt[nt[i]], 1);
}
__global__ void k_offsets() {
    g_off[0] = 0; g_off[1] = g_cnt[0]; g_off[2] = g_cnt[0] + g_cnt[1];
}
__global__ void k_scatter(const int* __restrict__ nt) {
    int i = blockIdx.x * blockDim.x + threadIdx.x;
    if (i < NN) {
        int t = nt[i];
        int p = atomicAdd(&g_fill[t], 1);
        g_order[g_off[t] + p] = i;
    }
}
__global__ void k_sinus() {      // grid(240), block(64)
    int p = blockIdx.x, d = threadIdx.x;
    double div = exp((double)(2 * d) * (-log(10000.0) / (double)NH_));
    double v = (double)p * div;
    double s = 1.0 / sqrt((double)NH_);
    g_sin[p*NH_ + 2*d]     = (float)(sin(v) * s);
    g_sin[p*NH_ + 2*d + 1] = (float)(cos(v) * s);
}
__global__ void k_zerodeg() {
    int i = blockIdx.x * blockDim.x + threadIdx.x;
    if (i < NN) { g_deg[i] = 0; g_dfill[i] = 0; }
}
__global__ void k_degcnt(const int* __restrict__ ei) {
    int e = blockIdx.x * blockDim.x + threadIdx.x;
    if (e < EE) atomicAdd(&g_deg[ei[EE + e]], 1);
}
__global__ __launch_bounds__(1024) void k_scan() {
    __shared__ int part[1024];
    int tid = threadIdx.x;
    const int CH = (NN + 1023) / 1024;
    int base = tid * CH;
    int s = 0;
    for (int i = 0; i < CH; i++) if (base + i < NN) s += g_deg[base + i];
    part[tid] = s;
    __syncthreads();
    for (int off = 1; off < 1024; off <<= 1) {
        int v = (tid >= off) ? part[tid - off] : 0;
        __syncthreads();
        part[tid] += v;
        __syncthreads();
    }
    int run = tid ? part[tid - 1] : 0;
    for (int i = 0; i < CH; i++)
        if (base + i < NN) { g_rowptr[base + i] = run; run += g_deg[base + i]; }
    if (tid == 1023) g_rowptr[NN] = part[1023];
}
__global__ void k_csrfill(const int* __restrict__ ei, const int* __restrict__ etime,
                          const int* __restrict__ et, const int* __restrict__ nt) {
    int e = blockIdx.x * blockDim.x + threadIdx.x;
    if (e >= EE) return;
    int src = ei[e], tgt = ei[EE + e];
    int ko = etime[e] * TT + nt[src];
    int pos = atomicAdd(&g_dfill[tgt], 1);
    int idx = g_rowptr[tgt] + pos;
    g_esrc[idx] = src;
    g_epk[idx]  = (ko << 2) | et[e];
}

// ---------------- per-layer small kernels ----------------
__global__ void k_rteproj(const float* __restrict__ rteW, const float* __restrict__ rteb) {
    int p = blockIdx.x, j = threadIdx.x;     // grid(240), block(128)
    const float* srow = g_sin + p*NH_;
    float acc = rteb[j];
    #pragma unroll 4
    for (int i = 0; i < NH_; i++) acc += srow[i] * __ldg(rteW + i*NH_ + j);
    g_t240[p*NH_ + j] = acc;
}
__global__ void k_ktvt(const float* __restrict__ kW, const float* __restrict__ vW) {
    int p = blockIdx.x, t = blockIdx.y, j = threadIdx.x;   // grid(240,3), block(128)
    const float* trow = g_t240 + p*NH_;
    const float* kw = kW + t*NH_*NH_;
    const float* vw = vW + t*NH_*NH_;
    float ak = 0.f, av = 0.f;
    #pragma unroll 4
    for (int i = 0; i < NH_; i++) {
        float tv = trow[i];
        ak += tv * __ldg(kw + i*NH_ + j);
        av += tv * __ldg(vw + i*NH_ + j);
    }
    g_kt[(p*TT + t)*NH_ + j] = ak;
    g_vt[(p*TT + t)*NH_ + j] = av;
}

// ---------------- type-bucketed GEMM ----------------
// MODE 0: none   MODE 1: tanh   MODE 2: gelu(X) on load + skip-mix epilogue
template<int KD, int MODE>
__global__ __launch_bounds__(256) void typed_gemm(
    const float* __restrict__ X, const float* __restrict__ Wt,
    const float* __restrict__ Bt, float* __restrict__ OUT,
    const float* __restrict__ HIN, const float* __restrict__ SK)
{
    __shared__ float xs[64*KD];
    __shared__ int rowNode[64];
    int b = blockIdx.x;
    int c0 = g_cnt[0], c1 = g_cnt[1], c2 = g_cnt[2];
    int n0 = (c0+63)>>6, n1 = (c1+63)>>6, n2 = (c2+63)>>6;
    int t, tile, cnt, off;
    if      (b < n0)       { t=0; tile=b;       cnt=c0; off=0;     }
    else if (b < n0+n1)    { t=1; tile=b-n0;    cnt=c1; off=c0;    }
    else if (b < n0+n1+n2) { t=2; tile=b-n0-n1; cnt=c2; off=c0+c1; }
    else return;
    int rbase = tile*64;
    int nrows = min(64, cnt - rbase);
    int tid = threadIdx.x;
    for (int i = tid; i < 64; i += 256)
        rowNode[i] = (i < nrows) ? g_order[off + rbase + i] : -1;
    __syncthreads();
    if (KD == 128) {
        for (int i = tid; i < 64*32; i += 256) {
            int row = i >> 5, c4 = i & 31;
            int nd = rowNode[row];
            float4 v = make_float4(0.f,0.f,0.f,0.f);
            if (nd >= 0) v = reinterpret_cast<const float4*>(X)[nd*32 + c4];
            if (MODE == 2) {
                v.x = 0.5f*v.x*(1.f + erff(v.x*0.70710678118654752f));
                v.y = 0.5f*v.y*(1.f + erff(v.y*0.70710678118654752f));
                v.z = 0.5f*v.z*(1.f + erff(v.z*0.70710678118654752f));
                v.w = 0.5f*v.w*(1.f + erff(v.w*0.70710678118654752f));
            }
            reinterpret_cast<float4*>(xs)[i] = v;
        }
    } else {
        for (int i = tid; i < 64*KD; i += 256) {
            int row = i / KD, c = i - row*KD;
            int nd = rowNode[row];
            xs[i] = (nd >= 0) ? X[nd*KD + c] : 0.f;
        }
    }
    __syncthreads();
    const float4* W4 = reinterpret_cast<const float4*>(Wt + t*KD*NH_);
    int c4 = tid & 31;
    int r0 = (tid >> 5) * 8;
    float acc[8][4] = {};
    #pragma unroll 2
    for (int i = 0; i < KD; i++) {
        float4 w = __ldg(&W4[i*32 + c4]);
        const float* xr = xs + r0*KD + i;
        #pragma unroll
        for (int rr = 0; rr < 8; rr++) {
            float xv = xr[rr*KD];
            acc[rr][0] += xv*w.x; acc[rr][1] += xv*w.y;
            acc[rr][2] += xv*w.z; acc[rr][3] += xv*w.w;
        }
    }
    float4 bb = reinterpret_cast<const float4*>(Bt + t*NH_)[c4];
    float alpha = 0.f;
    if (MODE == 2) alpha = 1.f / (1.f + expf(-SK[t]));
    #pragma unroll
    for (int rr = 0; rr < 8; rr++) {
        int nd = rowNode[r0 + rr];
        if (nd < 0) continue;
        float4 o = make_float4(acc[rr][0]+bb.x, acc[rr][1]+bb.y,
                               acc[rr][2]+bb.z, acc[rr][3]+bb.w);
        if (MODE == 1) {
            o.x = tanhf(o.x); o.y = tanhf(o.y); o.z = tanhf(o.z); o.w = tanhf(o.w);
        }
        if (MODE == 2) {
            float4 hv = reinterpret_cast<const float4*>(HIN)[nd*32 + c4];
            float beta = 1.f - alpha;
            o.x = o.x*alpha + hv.x*beta; o.y = o.y*alpha + hv.y*beta;
            o.z = o.z*alpha + hv.z*beta; o.w = o.w*alpha + hv.w*beta;
        }
        reinterpret_cast<float4*>(OUT)[nd*32 + c4] = o;
    }
}

// qrel[n,r,h,d] = sum_f rel_att[r,h,d,f] * q[n,h,f]
__global__ __launch_bounds__(128) void k_qrel(const float* __restrict__ A) {
    int r = blockIdx.y, tid = threadIdx.x;
    int h = tid >> 4, d = tid & 15;
    const float* Ap = A + ((r*HH + h)*16 + d)*16;
    float a[16];
    #pragma unroll
    for (int f = 0; f < 16; f++) a[f] = __ldg(Ap + f);
    __shared__ float qs[32*NH_];
    int nb = blockIdx.x * 32;
    for (int i = tid; i < 32*32; i += 128) {
        int row = i >> 5, c = i & 31;
        float4 v = make_float4(0.f,0.f,0.f,0.f);
        if (nb + row < NN) v = reinterpret_cast<const float4*>(g_q)[(nb+row)*32 + c];
        reinterpret_cast<float4*>(qs)[i] = v;
    }
    __syncthreads();
    int lim = min(32, NN - nb);
    for (int row = 0; row < lim; row++) {
        const float* qp = qs + row*NH_ + h*16;
        float acc = 0.f;
        #pragma unroll
        for (int f = 0; f < 16; f++) acc += a[f] * qp[f];
        g_qrel[((nb+row)*RR + r)*NH_ + tid] = acc;
    }
}

// ---------------- CSR edge pass: one warp per target node, no atomics --------
// agg[n,h,f] = (sum_e ex_e * sum_d v_e[h,d]*M[r,h,d,f]) / max(sum_e ex_e, 1e-9)
__global__ __launch_bounds__(256) void k_edge_csr(const float* __restrict__ pri,
                                                  const float* __restrict__ M) {
    int n = blockIdx.x*8 + (threadIdx.x >> 5);
    if (n >= NN) return;
    int lane = threadIdx.x & 31;
    int wl = threadIdx.x >> 5;
    int h = lane >> 2;
    __shared__ float qs[8][RR*NH_];   // 16KB: per-warp qrel[n, r, :]
    #pragma unroll
    for (int r = 0; r < RR; r++)
        reinterpret_cast<float4*>(qs[wl] + r*NH_)[lane] =
            reinterpret_cast<const float4*>(g_qrel)[(n*RR + r)*32 + lane];
    int beg = __ldg(g_rowptr + n), end = __ldg(g_rowptr + n + 1);
    float acc0 = 0.f, acc1 = 0.f, acc2 = 0.f, acc3 = 0.f;
    float den = 0.f;
    int qbase = lane & ~3;
    for (int j = beg; j < end; j++) {
        int src = __ldg(g_esrc + j);
        int pk  = __ldg(g_epk + j);
        int r = pk & 3, ko = pk >> 2;
        // attention logit for head h
        float4 k  = reinterpret_cast<const float4*>(g_kn)[src*32 + lane];
        float4 kt = reinterpret_cast<const float4*>(g_kt)[ko*32 + lane];
        float4 q  = reinterpret_cast<const float4*>(qs[wl] + r*NH_)[lane];
        float dot = (k.x+kt.x)*q.x + (k.y+kt.y)*q.y + (k.z+kt.z)*q.z + (k.w+kt.w)*q.w;
        dot += __shfl_xor_sync(0xffffffffu, dot, 1);
        dot += __shfl_xor_sync(0xffffffffu, dot, 2);
        float ex = expf(dot * __ldg(pri + r*HH + h) * 0.25f);
        den += ex;
        // message: v_rel
        float4 va = reinterpret_cast<const float4*>(g_vn)[src*32 + lane];
        float4 vb = reinterpret_cast<const float4*>(g_vt)[ko*32 + lane];
        float vreg[4] = {va.x+vb.x, va.y+vb.y, va.z+vb.z, va.w+vb.w};
        const float4* M4 = reinterpret_cast<const float4*>(M) + ((r*HH + h)*16)*4 + (lane & 3);
        float mx = 0.f, my = 0.f, mz = 0.f, mw = 0.f;
        #pragma unroll
        for (int jj = 0; jj < 4; jj++) {
            #pragma unroll
            for (int ii = 0; ii < 4; ii++) {
                float vd = __shfl_sync(0xffffffffu, vreg[ii], qbase + jj);
                float4 m = __ldg(M4 + (4*jj + ii)*4);
                mx += vd*m.x; my += vd*m.y; mz += vd*m.z; mw += vd*m.w;
            }
        }
        acc0 += ex*mx; acc1 += ex*my; acc2 += ex*mz; acc3 += ex*mw;
    }
    float inv = 1.f / fmaxf(den, 1e-9f);
    float4 o = make_float4(acc0*inv, acc1*inv, acc2*inv, acc3*inv);
    reinterpret_cast<float4*>(g_agg)[n*32 + lane] = o;
}

extern "C" void kernel_launch(void* const* d_in, const int* in_sizes, int n_in,
                              void* d_out, int out_size) {
    const float* node_feature = (const float*)d_in[0];
    const int*   node_type    = (const int*)  d_in[1];
    const int*   etime = (const int*)d_in[2];
    const int*   ei    = (const int*)d_in[3];
    const int*   et    = (const int*)d_in[4];
    const float* adapt_W = (const float*)d_in[5];
    const float* adapt_b = (const float*)d_in[6];
    const float* kW = (const float*)d_in[7];
    const float* kb = (const float*)d_in[8];
    const float* qW = (const float*)d_in[9];
    const float* qb = (const float*)d_in[10];
    const float* vW = (const float*)d_in[11];
    const float* vb = (const float*)d_in[12];
    const float* aW = (const float*)d_in[13];
    const float* ab = (const float*)d_in[14];
    const float* rel_att = (const float*)d_in[15];
    const float* rel_msg = (const float*)d_in[16];
    const float* rel_pri = (const float*)d_in[17];
    const float* skip = (const float*)d_in[18];
    const float* rteW = (const float*)d_in[19];
    const float* rteb = (const float*)d_in[20];
    float* out = (float*)d_out;

    float *p_h, *p_h2, *p_q, *p_kn, *p_vn, *p_agg;
    cudaGetSymbolAddress((void**)&p_h,   g_h);
    cudaGetSymbolAddress((void**)&p_h2,  g_h2);
    cudaGetSymbolAddress((void**)&p_q,   g_q);
    cudaGetSymbolAddress((void**)&p_kn,  g_kn);
    cudaGetSymbolAddress((void**)&p_vn,  g_vn);
    cudaGetSymbolAddress((void**)&p_agg, g_agg);

    const int GEMM_BLKS = (NN + 63)/64 + TT - 1;

    // prologue: type buckets + CSR by target
    k_init<<<1, 32>>>();
    k_count<<<cdiv(NN,256), 256>>>(node_type);
    k_offsets<<<1, 1>>>();
    k_scatter<<<cdiv(NN,256), 256>>>(node_type);
    k_sinus<<<MT_, 64>>>();
    k_zerodeg<<<cdiv(NN,256), 256>>>();
    k_degcnt<<<cdiv(EE,256), 256>>>(ei);
    k_scan<<<1, 1024>>>();
    k_csrfill<<<cdiv(EE,256), 256>>>(ei, etime, et, node_type);
    typed_gemm<DIN_,1><<<GEMM_BLKS, 256>>>(node_feature, adapt_W, adapt_b, p_h,
                                           nullptr, nullptr);

    const float* h_in = p_h;
    for (int l = 0; l < LL; l++) {
        const float* qW_l = qW + l*TT*NH_*NH_;
        const float* qb_l = qb + l*TT*NH_;
        const float* kW_l = kW + l*TT*NH_*NH_;
        const float* kb_l = kb + l*TT*NH_;
        const float* vW_l = vW + l*TT*NH_*NH_;
        const float* vb_l = vb + l*TT*NH_;
        const float* aW_l = aW + l*TT*NH_*NH_;
        const float* ab_l = ab + l*TT*NH_;
        const float* ratt = rel_att + l*RR*HH*256;
        const float* rmsg = rel_msg + l*RR*HH*256;
        const float* pri  = rel_pri + l*RR*HH;
        const float* sk   = skip + l*TT;
        float* h_out = (l == LL-1) ? out : p_h2;

        typed_gemm<NH_,0><<<GEMM_BLKS, 256>>>(h_in, qW_l, qb_l, p_q,  nullptr, nullptr);
        typed_gemm<NH_,0><<<GEMM_BLKS, 256>>>(h_in, kW_l, kb_l, p_kn, nullptr, nullptr);
        typed_gemm<NH_,0><<<GEMM_BLKS, 256>>>(h_in, vW_l, vb_l, p_vn, nullptr, nullptr);
        k_rteproj<<<MT_, 128>>>(rteW + l*NH_*NH_, rteb + l*NH_);
        k_ktvt<<<dim3(MT_, TT), 128>>>(kW_l, vW_l);
        k_qrel<<<dim3(cdiv(NN,32), RR), 128>>>(ratt);
        k_edge_csr<<<cdiv(NN,8), 256>>>(pri, rmsg);
        typed_gemm<NH_,2><<<GEMM_BLKS, 256>>>(p_agg, aW_l, ab_l, h_out, h_in, sk);

        h_in = h_out;
    }
}